// round 12
// baseline (speedup 1.0000x reference)
#include <cuda_runtime.h>
#include <cuda_bf16.h>

#define FDIM 128
#define PDIST 8            // L2 prefetch distance in rows
#define MAXG  (1 << 20)    // max supported num_graphs for the boundary scratch
#define GPW_A 2            // graphs per atom warp (~100 rows)
#define GPW_V 8            // graphs per vir  warp (~32 rows)

// Scratch: bound[g] = first row index with seg >= g (per side); bound[G] = n.
__device__ int g_bound_atom[MAXG + 2];
__device__ int g_bound_vir [MAXG + 2];

__device__ __forceinline__ void prefetch_l2(const void* p) {
    asm volatile("prefetch.global.L2 [%0];" :: "l"(p));
}
__device__ __forceinline__ void stg_cs_f32(float* addr, float v) {
    asm volatile("st.global.cs.f32 [%0], %1;" :: "l"(addr), "f"(v) : "memory");
}
__device__ __forceinline__ void stg_cs_v4(float* addr, float4 v) {
    asm volatile("st.global.cs.v4.f32 [%0], {%1, %2, %3, %4};"
                 :: "l"(addr), "f"(v.x), "f"(v.y), "f"(v.z), "f"(v.w)
                 : "memory");
}
__device__ __forceinline__ float sigmoidf_fast(float x) {
    return 1.0f / (1.0f + __expf(-x));
}

// ---------------------------------------------------------------------------
// Kernel 1: segment boundaries, 4 rows per thread via int4.
// Row i writes bound[g] = i for every g in (seg[i-1], seg[i]]; last row fills
// the tail with n_rows. Each bound slot written by exactly one thread.
// ---------------------------------------------------------------------------
__device__ __forceinline__ void bounds_for4(const int* __restrict__ seg, int n,
                                            int* __restrict__ bound,
                                            int base, int num_graphs)
{
    if (base >= n) return;
    const int4 s4 = *reinterpret_cast<const int4*>(seg + base);   // base % 4 == 0
    int s[4] = {s4.x, s4.y, s4.z, s4.w};
    int prev = (base == 0) ? -1 : __ldg(seg + base - 1);
    #pragma unroll
    for (int k = 0; k < 4; ++k) {
        const int i = base + k;
        if (i < n) {
            for (int g = prev + 1; g <= s[k]; ++g) bound[g] = i;
            if (i == n - 1)
                for (int g = s[k] + 1; g <= num_graphs; ++g) bound[g] = n;
            prev = s[k];
        }
    }
}

__global__ void boundary_kernel(const int* __restrict__ atom_seg, int n_atom,
                                const int* __restrict__ vir_seg,  int n_vir,
                                int num_graphs)
{
    const int t = blockIdx.x * blockDim.x + threadIdx.x;
    const int atom_threads = (n_atom + 3) / 4;
    if (t < atom_threads) {
        bounds_for4(atom_seg, n_atom, g_bound_atom, t * 4, num_graphs);
    } else {
        const int j = t - atom_threads;
        bounds_for4(vir_seg, n_vir, g_bound_vir, j * 4, num_graphs);
    }
}

// ---------------------------------------------------------------------------
// Kernel 2: one warp owns GPW consecutive graphs = ONE contiguous row range.
// Single unroll-4 pipeline over the whole range (no per-graph restarts);
// flush acc via plain st.cs.v4 exactly when crossing a boundary (boundary
// values reloaded from the L1-hot bound array). No seg loads, no atomics.
// Lane l owns features [4l, 4l+4).
// ---------------------------------------------------------------------------
template <bool WRITE_LOGITS>
__device__ __forceinline__ void run_group(const float* __restrict__ feats,
                                          const float4 w4, const float bias,
                                          const int* __restrict__ bound,
                                          int g0, int g1, int n_rows,
                                          float* __restrict__ out_sum,
                                          float* __restrict__ out_logits,
                                          int lane)
{
    int r        = bound[g0];          // lane-uniform (broadcast) loads
    const int rE = bound[g1];
    int g        = g0;
    int next_end = bound[g0 + 1];
    float* outp  = out_sum + (size_t)g0 * FDIM + lane * 4;

    float4 acc = make_float4(0.f, 0.f, 0.f, 0.f);

    while (r + 4 <= rE) {
        const float4 f0 = *reinterpret_cast<const float4*>(feats + (size_t)(r + 0) * FDIM + lane * 4);
        const float4 f1 = *reinterpret_cast<const float4*>(feats + (size_t)(r + 1) * FDIM + lane * 4);
        const float4 f2 = *reinterpret_cast<const float4*>(feats + (size_t)(r + 2) * FDIM + lane * 4);
        const float4 f3 = *reinterpret_cast<const float4*>(feats + (size_t)(r + 3) * FDIM + lane * 4);

        // L2 prefetch (spilling past the group's end is still useful work).
        #pragma unroll
        for (int i = 0; i < 4; ++i) {
            const int pr = r + PDIST + i;
            if (pr < n_rows)
                prefetch_l2(feats + (size_t)pr * FDIM + lane * 4);
        }

        float p0 = f0.x * w4.x + f0.y * w4.y + f0.z * w4.z + f0.w * w4.w;
        float p1 = f1.x * w4.x + f1.y * w4.y + f1.z * w4.z + f1.w * w4.w;
        float p2 = f2.x * w4.x + f2.y * w4.y + f2.z * w4.z + f2.w * w4.w;
        float p3 = f3.x * w4.x + f3.y * w4.y + f3.z * w4.z + f3.w * w4.w;

        #pragma unroll
        for (int o = 16; o > 0; o >>= 1) {
            p0 += __shfl_xor_sync(0xffffffffu, p0, o);
            p1 += __shfl_xor_sync(0xffffffffu, p1, o);
            p2 += __shfl_xor_sync(0xffffffffu, p2, o);
            p3 += __shfl_xor_sync(0xffffffffu, p3, o);
        }
        p0 += bias; p1 += bias; p2 += bias; p3 += bias;

        if (WRITE_LOGITS && lane == 0) {
            stg_cs_f32(out_logits + r + 0, p0);
            stg_cs_f32(out_logits + r + 1, p1);
            stg_cs_f32(out_logits + r + 2, p2);
            stg_cs_f32(out_logits + r + 3, p3);
        }

        const float q0 = sigmoidf_fast(p0);
        const float q1 = sigmoidf_fast(p1);
        const float q2 = sigmoidf_fast(p2);
        const float q3 = sigmoidf_fast(p3);

        if (r + 4 <= next_end) {
            // Fast path: whole group inside current graph.
            acc.x += q0 * f0.x; acc.y += q0 * f0.y; acc.z += q0 * f0.z; acc.w += q0 * f0.w;
            acc.x += q1 * f1.x; acc.y += q1 * f1.y; acc.z += q1 * f1.z; acc.w += q1 * f1.w;
            acc.x += q2 * f2.x; acc.y += q2 * f2.y; acc.z += q2 * f2.z; acc.w += q2 * f2.w;
            acc.x += q3 * f3.x; acc.y += q3 * f3.y; acc.z += q3 * f3.z; acc.w += q3 * f3.w;
        } else {
            const float  qs[4] = {q0, q1, q2, q3};
            const float4 fs[4] = {f0, f1, f2, f3};
            #pragma unroll
            for (int i = 0; i < 4; ++i) {
                const int rr = r + i;
                while (rr == next_end) {     // handles empty graphs too
                    stg_cs_v4(outp, acc);
                    acc = make_float4(0.f, 0.f, 0.f, 0.f);
                    outp += FDIM; ++g;
                    next_end = bound[g + 1];
                }
                acc.x += qs[i] * fs[i].x; acc.y += qs[i] * fs[i].y;
                acc.z += qs[i] * fs[i].z; acc.w += qs[i] * fs[i].w;
            }
        }
        r += 4;
    }

    // Tail rows (< 4 remaining in the whole range).
    for (; r < rE; ++r) {
        const float4 f = *reinterpret_cast<const float4*>(feats + (size_t)r * FDIM + lane * 4);
        float p = f.x * w4.x + f.y * w4.y + f.z * w4.z + f.w * w4.w;
        #pragma unroll
        for (int o = 16; o > 0; o >>= 1)
            p += __shfl_xor_sync(0xffffffffu, p, o);
        p += bias;
        if (WRITE_LOGITS && lane == 0) stg_cs_f32(out_logits + r, p);
        const float q = sigmoidf_fast(p);
        while (r == next_end) {
            stg_cs_v4(outp, acc);
            acc = make_float4(0.f, 0.f, 0.f, 0.f);
            outp += FDIM; ++g;
            next_end = bound[g + 1];
        }
        acc.x += q * f.x; acc.y += q * f.y; acc.z += q * f.z; acc.w += q * f.w;
    }

    // Final flush: current graph + any trailing empty graphs.
    while (g < g1) {
        stg_cs_v4(outp, acc);
        acc = make_float4(0.f, 0.f, 0.f, 0.f);
        outp += FDIM; ++g;
    }
}

__global__ __launch_bounds__(256, 4)
void fused_gated_segsum(const float* __restrict__ atom_feats,
                        const float* __restrict__ W_atom,
                        const float* __restrict__ b_atom,
                        int n_atom,
                        const float* __restrict__ vir_feats,
                        const float* __restrict__ W_vir,
                        const float* __restrict__ b_vir,
                        int n_vir,
                        int num_graphs,
                        float* __restrict__ sum_atom,
                        float* __restrict__ sum_vir,
                        float* __restrict__ logits)
{
    const int warp = (int)((blockIdx.x * blockDim.x + threadIdx.x) >> 5);
    const int lane = threadIdx.x & 31;

    const int atom_groups = (num_graphs + GPW_A - 1) / GPW_A;
    const int vir_groups  = (num_graphs + GPW_V - 1) / GPW_V;

    if (warp < atom_groups) {
        const float4 w4  = *reinterpret_cast<const float4*>(W_atom + lane * 4);
        const float bias = __ldg(b_atom);
        const int g0 = warp * GPW_A;
        const int g1 = min(num_graphs, g0 + GPW_A);
        run_group<true>(atom_feats, w4, bias, g_bound_atom, g0, g1, n_atom,
                        sum_atom, logits, lane);
    } else if (warp < atom_groups + vir_groups) {
        const int w = warp - atom_groups;
        const float4 w4  = *reinterpret_cast<const float4*>(W_vir + lane * 4);
        const float bias = __ldg(b_vir);
        const int g0 = w * GPW_V;
        const int g1 = min(num_graphs, g0 + GPW_V);
        run_group<false>(vir_feats, w4, bias, g_bound_vir, g0, g1, n_vir,
                         sum_vir, nullptr, lane);
    }
}

extern "C" void kernel_launch(void* const* d_in, const int* in_sizes, int n_in,
                              void* d_out, int out_size) {
    const float* atom_feats = (const float*)d_in[0];
    const float* vir_feats  = (const float*)d_in[1];
    const float* W_atom     = (const float*)d_in[2];
    const float* b_atom     = (const float*)d_in[3];
    const float* W_vir      = (const float*)d_in[4];
    const float* b_vir      = (const float*)d_in[5];
    const int*   atom_seg   = (const int*)d_in[6];
    const int*   vir_seg    = (const int*)d_in[7];

    const int n_atom = in_sizes[0] / FDIM;
    const int n_vir  = in_sizes[1] / FDIM;
    const int num_graphs = (out_size - n_atom) / (2 * FDIM);

    float* out      = (float*)d_out;
    float* sum_atom = out;
    float* sum_vir  = out + (size_t)num_graphs * FDIM;
    float* logits   = out + (size_t)num_graphs * FDIM * 2;

    // Kernel 1: segment boundaries (4 rows/thread). No memset anywhere.
    {
        const int threads = (n_atom + 3) / 4 + (n_vir + 3) / 4;
        boundary_kernel<<<(threads + 255) / 256, 256>>>(
            atom_seg, n_atom, vir_seg, n_vir, num_graphs);
    }

    // Kernel 2: contiguous-stream gated sums + logits, write-once outputs.
    {
        const int atom_groups = (num_graphs + GPW_A - 1) / GPW_A;
        const int vir_groups  = (num_graphs + GPW_V - 1) / GPW_V;
        const int total_warps = atom_groups + vir_groups;
        const int blocks = (total_warps + 7) / 8;   // 8 warps / CTA
        fused_gated_segsum<<<blocks, 256>>>(
            atom_feats, W_atom, b_atom, n_atom,
            vir_feats,  W_vir,  b_vir,  n_vir,
            num_graphs, sum_atom, sum_vir, logits);
    }
}